// round 3
// baseline (speedup 1.0000x reference)
#include <cuda_runtime.h>
#include <cuda_bf16.h>
#include <math.h>

#define NODES 22528
#define EDGES 360448
#define FEA   60
#define HID   512
#define CATW  572            // HID + FEA
#define BATCH 1024           // NODES / 22
#define FLATK (22*CATW)      // 12584
#define SLOPE 0.01f

// ---------------- scratch (__device__ globals; no allocation allowed) ----------------
__device__ float g_bufA[(size_t)NODES * HID];     // 46 MB
__device__ float g_bufB[(size_t)NODES * HID];     // 46 MB
__device__ float g_cat [(size_t)NODES * CATW];    // 51.5 MB  == [BATCH, FLATK]
__device__ float g_degw[NODES];
__device__ float g_dis [NODES];
__device__ int   g_cnt [NODES];
__device__ int   g_fill[NODES];
__device__ int   g_rowptr[NODES + 1];
__device__ int   g_csr_src[EDGES];
__device__ float g_csr_w [EDGES];
__device__ float g_m0[BATCH * HID];
__device__ float g_m1[BATCH * HID];
__device__ int   g_nz;        // nonzero odd-word count (dtype probe)
__device__ int   g_is64;      // 1 if edge_index is int64

// buffer selector ids
#define SEL_EXT 0
#define SEL_A   1
#define SEL_B   2
#define SEL_CAT 3
#define SEL_M0  4
#define SEL_M1  5

__device__ __forceinline__ float* selbuf(int id) {
    switch (id) {
        case SEL_A:   return g_bufA;
        case SEL_B:   return g_bufB;
        case SEL_CAT: return g_cat;
        case SEL_M0:  return g_m0;
        default:      return g_m1;
    }
}

__device__ __forceinline__ float lrelu(float v) { return v > 0.f ? v : SLOPE * v; }

// fetch logical element `idx` of edge_index (layout [2, EDGES]) under either dtype
__device__ __forceinline__ int edge_val(const int* __restrict__ ei32, int idx) {
    return g_is64 ? ei32[2 * (size_t)idx] : ei32[idx];
}

// ---------------- dtype probe ----------------
// int32 data: odd int32 positions hold genuine random indices (virtually never all zero).
// int64 data (values < 2^31, little-endian): odd positions are high words == 0.
__global__ void k_probe(const int* __restrict__ ei32) {
    int t = threadIdx.x + blockIdx.x * blockDim.x;
    if (t == 0) g_nz = 0;
    __threadfence();
    int v = ei32[2 * t + 1];           // sample first 2048 odd words
    if (v != 0) atomicAdd(&g_nz, 1);
}
__global__ void k_probe_fin() { g_is64 = (g_nz == 0) ? 1 : 0; }

// ---------------- graph preprocessing ----------------
__global__ void k_init() {
    int i = blockIdx.x * blockDim.x + threadIdx.x;
    if (i < NODES) { g_degw[i] = 1.0f; g_cnt[i] = 0; g_fill[i] = 0; }
}

__global__ void k_edge_deg(const int* __restrict__ ei, const float* __restrict__ ew) {
    int e = blockIdx.x * blockDim.x + threadIdx.x;
    if (e < EDGES) {
        int dst = edge_val(ei, EDGES + e);
        atomicAdd(&g_degw[dst], ew[e]);
        atomicAdd(&g_cnt[dst], 1);
    }
}

__global__ void k_dis() {
    int i = blockIdx.x * blockDim.x + threadIdx.x;
    if (i < NODES) g_dis[i] = rsqrtf(g_degw[i]);   // deg >= 1 always (self-loop)
}

// exclusive scan of g_cnt -> g_rowptr. NODES = 1024 * 22 exactly; single block.
__global__ void k_scan() {
    __shared__ int ssum[1024];
    int t = threadIdx.x;
    int base = t * 22;
    int vals[22];
    int local = 0;
#pragma unroll
    for (int i = 0; i < 22; i++) { vals[i] = g_cnt[base + i]; local += vals[i]; }
    ssum[t] = local;
    __syncthreads();
    for (int off = 1; off < 1024; off <<= 1) {
        int v = (t >= off) ? ssum[t - off] : 0;
        __syncthreads();
        ssum[t] += v;
        __syncthreads();
    }
    int prefix = (t == 0) ? 0 : ssum[t - 1];
#pragma unroll
    for (int i = 0; i < 22; i++) { g_rowptr[base + i] = prefix; prefix += vals[i]; }
    if (t == 1023) g_rowptr[NODES] = prefix;
}

__global__ void k_fill(const int* __restrict__ ei, const float* __restrict__ ew) {
    int e = blockIdx.x * blockDim.x + threadIdx.x;
    if (e < EDGES) {
        int src = edge_val(ei, e);
        int dst = edge_val(ei, EDGES + e);
        int pos = g_rowptr[dst] + atomicAdd(&g_fill[dst], 1);
        g_csr_src[pos] = src;
        g_csr_w[pos]   = g_dis[src] * ew[e] * g_dis[dst];
    }
}

// ---------------- SpMM aggregation: out[n] = lrelu(bias + sum_e w*h[src]) ----------------
// one block (128 threads) per node; each thread owns one float4 of the 512-wide row.
__global__ __launch_bounds__(128) void k_agg(int hsel,
                                             const float* __restrict__ bias,
                                             int osel, int ostride) {
    const float* h = selbuf(hsel);
    float* out = selbuf(osel);
    int node = blockIdx.x;
    int f = threadIdx.x;                   // 0..127 float4 lanes
    float sw = g_dis[node]; sw *= sw;      // self-loop norm
    const float4* hrow = (const float4*)(h + (size_t)node * HID);
    float4 v = __ldg(hrow + f);
    float4 acc = make_float4(sw * v.x, sw * v.y, sw * v.z, sw * v.w);
    int s = g_rowptr[node], e = g_rowptr[node + 1];
    for (int j = s; j < e; j++) {
        int   src = g_csr_src[j];
        float w   = g_csr_w[j];
        float4 u = __ldg(((const float4*)(h + (size_t)src * HID)) + f);
        acc.x += w * u.x; acc.y += w * u.y; acc.z += w * u.z; acc.w += w * u.w;
    }
    float4 b = __ldg(((const float4*)bias) + f);
    acc.x = lrelu(acc.x + b.x);
    acc.y = lrelu(acc.y + b.y);
    acc.z = lrelu(acc.z + b.z);
    acc.w = lrelu(acc.w + b.w);
    *(float4*)(out + (size_t)node * ostride + 4 * f) = acc;
}

// copy x into cat[:, 512:572]
__global__ void k_catx(const float* __restrict__ x) {
    int node = blockIdx.x;
    int t = threadIdx.x;
    if (t < FEA) g_cat[(size_t)node * CATW + HID + t] = x[(size_t)node * FEA + t];
}

// ---------------- SGEMM: C = act(A[M,K] @ B[K,N] + bias) ----------------
// 64x64 tile, BK=16, 256 threads, 4x4 per thread. M % 64 == 0, N % 64 == 0 assumed.
template<bool BIAS, bool RELU>
__global__ __launch_bounds__(256) void sgemm64(const float* __restrict__ Aext, int asel,
                                               const float* __restrict__ B,
                                               const float* __restrict__ bias,
                                               int csel,
                                               int M, int N, int K) {
    const float* A = (asel == SEL_EXT) ? Aext : selbuf(asel);
    float* C = selbuf(csel);
    __shared__ float As[16][68];
    __shared__ float Bs[16][64];
    int tid = threadIdx.x;
    int bm = blockIdx.y * 64, bn = blockIdx.x * 64;
    int tx = tid & 15, ty = tid >> 4;
    int aRow = tid >> 2;
    int aK   = (tid & 3) * 4;

    float acc[4][4];
#pragma unroll
    for (int i = 0; i < 4; i++)
#pragma unroll
        for (int j = 0; j < 4; j++) acc[i][j] = 0.f;

    for (int k0 = 0; k0 < K; k0 += 16) {
        int kA = k0 + aK;
        const float* ap = A + (size_t)(bm + aRow) * K + kA;
        float4 av = make_float4(0.f, 0.f, 0.f, 0.f);
        if (kA + 3 < K) {
            av = *(const float4*)ap;
        } else {
            if (kA + 0 < K) av.x = ap[0];
            if (kA + 1 < K) av.y = ap[1];
            if (kA + 2 < K) av.z = ap[2];
            if (kA + 3 < K) av.w = ap[3];
        }
        As[aK + 0][aRow] = av.x;
        As[aK + 1][aRow] = av.y;
        As[aK + 2][aRow] = av.z;
        As[aK + 3][aRow] = av.w;
#pragma unroll
        for (int i = 0; i < 4; i++) {
            int idx = tid + i * 256;
            int bk = idx >> 6, bc = idx & 63;
            float v = 0.f;
            if (k0 + bk < K) v = B[(size_t)(k0 + bk) * N + bn + bc];
            Bs[bk][bc] = v;
        }
        __syncthreads();
#pragma unroll
        for (int kk = 0; kk < 16; kk++) {
            float a0 = As[kk][ty * 4 + 0], a1 = As[kk][ty * 4 + 1];
            float a2 = As[kk][ty * 4 + 2], a3 = As[kk][ty * 4 + 3];
            float b0 = Bs[kk][tx * 4 + 0], b1 = Bs[kk][tx * 4 + 1];
            float b2 = Bs[kk][tx * 4 + 2], b3 = Bs[kk][tx * 4 + 3];
            acc[0][0] += a0 * b0; acc[0][1] += a0 * b1; acc[0][2] += a0 * b2; acc[0][3] += a0 * b3;
            acc[1][0] += a1 * b0; acc[1][1] += a1 * b1; acc[1][2] += a1 * b2; acc[1][3] += a1 * b3;
            acc[2][0] += a2 * b0; acc[2][1] += a2 * b1; acc[2][2] += a2 * b2; acc[2][3] += a2 * b3;
            acc[3][0] += a3 * b0; acc[3][1] += a3 * b1; acc[3][2] += a3 * b2; acc[3][3] += a3 * b3;
        }
        __syncthreads();
    }

#pragma unroll
    for (int i = 0; i < 4; i++) {
        int row = bm + ty * 4 + i;
        int col = bn + tx * 4;
        float4 r = make_float4(acc[i][0], acc[i][1], acc[i][2], acc[i][3]);
        if (BIAS) {
            float4 bb = *(const float4*)(bias + col);
            r.x += bb.x; r.y += bb.y; r.z += bb.z; r.w += bb.w;
        }
        if (RELU) { r.x = lrelu(r.x); r.y = lrelu(r.y); r.z = lrelu(r.z); r.w = lrelu(r.w); }
        *(float4*)(C + (size_t)row * N + col) = r;
    }
}

// ---------------- head: logits = g_m0@Wo + bo, then log_softmax over 4 ----------------
__global__ __launch_bounds__(128) void k_final(const float* __restrict__ Wo,
                                               const float* __restrict__ bo,
                                               float* __restrict__ out) {
    int warp = threadIdx.x >> 5, lane = threadIdx.x & 31;
    int row = blockIdx.x * 4 + warp;
    const float* hr = g_m0 + (size_t)row * HID;
    float a0 = 0.f, a1 = 0.f, a2 = 0.f, a3 = 0.f;
    for (int k = lane; k < HID; k += 32) {
        float hv = hr[k];
        float4 w = ((const float4*)Wo)[k];
        a0 += hv * w.x; a1 += hv * w.y; a2 += hv * w.z; a3 += hv * w.w;
    }
#pragma unroll
    for (int off = 16; off; off >>= 1) {
        a0 += __shfl_xor_sync(0xffffffffu, a0, off);
        a1 += __shfl_xor_sync(0xffffffffu, a1, off);
        a2 += __shfl_xor_sync(0xffffffffu, a2, off);
        a3 += __shfl_xor_sync(0xffffffffu, a3, off);
    }
    if (lane == 0) {
        a0 += bo[0]; a1 += bo[1]; a2 += bo[2]; a3 += bo[3];
        float m = fmaxf(fmaxf(a0, a1), fmaxf(a2, a3));
        float s = expf(a0 - m) + expf(a1 - m) + expf(a2 - m) + expf(a3 - m);
        float lse = m + logf(s);
        out[row * 4 + 0] = a0 - lse;
        out[row * 4 + 1] = a1 - lse;
        out[row * 4 + 2] = a2 - lse;
        out[row * 4 + 3] = a3 - lse;
    }
}

// ---------------- launch ----------------
extern "C" void kernel_launch(void* const* d_in, const int* in_sizes, int n_in,
                              void* d_out, int out_size) {
    const float* x   = (const float*)d_in[0];
    const int*   ei  = (const int*)d_in[1];        // int32 OR int64 (probed on device)
    const float* ew  = (const float*)d_in[2];
    const float* W1  = (const float*)d_in[3];
    const float* b1  = (const float*)d_in[4];
    const float* W2  = (const float*)d_in[5];
    const float* b2  = (const float*)d_in[6];
    const float* Wf0 = (const float*)d_in[7];
    const float* bf0 = (const float*)d_in[8];
    const float* Wf1 = (const float*)d_in[9];
    const float* bf1 = (const float*)d_in[10];
    const float* Wf2 = (const float*)d_in[11];
    const float* bf2 = (const float*)d_in[12];
    const float* Wo  = (const float*)d_in[13];
    const float* bo  = (const float*)d_in[14];
    float* out = (float*)d_out;

    // dtype probe (samples words within the first 4096 int32s = safe for either dtype)
    k_probe<<<8, 256>>>(ei);
    k_probe_fin<<<1, 1>>>();

    // CSR build
    k_init<<<(NODES + 255) / 256, 256>>>();
    k_edge_deg<<<(EDGES + 255) / 256, 256>>>(ei, ew);
    k_dis<<<(NODES + 255) / 256, 256>>>();
    k_scan<<<1, 1024>>>();
    k_fill<<<(EDGES + 255) / 256, 256>>>(ei, ew);

    // conv1: bufA = x@W1 ; bufB = lrelu(agg(bufA) + b1)
    sgemm64<false, false><<<dim3(HID / 64, NODES / 64), 256>>>(x, SEL_EXT, W1, nullptr, SEL_A, NODES, HID, FEA);
    k_agg<<<NODES, 128>>>(SEL_A, b1, SEL_B, HID);

    // conv2: bufA = bufB@W2 ; cat[:, :512] = lrelu(agg(bufA) + b2)
    sgemm64<false, false><<<dim3(HID / 64, NODES / 64), 256>>>(nullptr, SEL_B, W2, nullptr, SEL_A, NODES, HID, HID);
    k_agg<<<NODES, 128>>>(SEL_A, b2, SEL_CAT, CATW);
    k_catx<<<NODES, 64>>>(x);

    // MLP (cat viewed as [1024, 12584])
    sgemm64<true, true><<<dim3(HID / 64, BATCH / 64), 256>>>(nullptr, SEL_CAT, Wf0, bf0, SEL_M0, BATCH, HID, FLATK);
    sgemm64<true, true><<<dim3(HID / 64, BATCH / 64), 256>>>(nullptr, SEL_M0, Wf1, bf1, SEL_M1, BATCH, HID, HID);
    sgemm64<true, true><<<dim3(HID / 64, BATCH / 64), 256>>>(nullptr, SEL_M1, Wf2, bf2, SEL_M0, BATCH, HID, HID);

    // head + log_softmax
    k_final<<<BATCH / 4, 128>>>(Wo, bo, out);
}

// round 4
// speedup vs baseline: 1.0003x; 1.0003x over previous
#include <cuda_runtime.h>
#include <cuda_bf16.h>
#include <math.h>

#define NODES 22528
#define EDGES 360448
#define FEA   60
#define HID   512
#define CATW  572            // HID + FEA
#define BATCH 1024           // NODES / 22
#define FLATK (22*CATW)      // 12584
#define SLOPE 0.01f

// ---------------- scratch (__device__ globals; no allocation allowed) ----------------
__device__ float g_bufA[(size_t)NODES * HID];     // 46 MB
__device__ float g_bufB[(size_t)NODES * HID];     // 46 MB
__device__ float g_cat [(size_t)NODES * CATW];    // 51.5 MB  == [BATCH, FLATK]
__device__ float g_degw[NODES];
__device__ float g_dis [NODES];
__device__ int   g_cnt [NODES];
__device__ int   g_fill[NODES];
__device__ int   g_rowptr[NODES + 1];
__device__ int   g_csr_src[EDGES];
__device__ float g_csr_w [EDGES];
__device__ float g_m0[BATCH * HID];
__device__ float g_m1[BATCH * HID];
__device__ int   g_nz;        // nonzero odd-word count (dtype probe)
__device__ int   g_is64;      // 1 if edge_index is int64

// buffer selector ids
#define SEL_EXT 0
#define SEL_A   1
#define SEL_B   2
#define SEL_CAT 3
#define SEL_M0  4
#define SEL_M1  5

__device__ __forceinline__ float* selbuf(int id) {
    switch (id) {
        case SEL_A:   return g_bufA;
        case SEL_B:   return g_bufB;
        case SEL_CAT: return g_cat;
        case SEL_M0:  return g_m0;
        default:      return g_m1;
    }
}

__device__ __forceinline__ float lrelu(float v) { return v > 0.f ? v : SLOPE * v; }

// fetch logical element `idx` of edge_index (layout [2, EDGES]) under either dtype
__device__ __forceinline__ int edge_val(const int* __restrict__ ei32, int idx) {
    return g_is64 ? ei32[2 * (size_t)idx] : ei32[idx];
}

// ---------------- dtype probe ----------------
// int32 data: odd int32 positions hold genuine random indices (virtually never all zero).
// int64 data (values < 2^31, little-endian): odd positions are high words == 0.
__global__ void k_probe(const int* __restrict__ ei32) {
    int t = threadIdx.x + blockIdx.x * blockDim.x;
    if (t == 0) g_nz = 0;
    __threadfence();
    int v = ei32[2 * t + 1];           // sample first 2048 odd words
    if (v != 0) atomicAdd(&g_nz, 1);
}
__global__ void k_probe_fin() { g_is64 = (g_nz == 0) ? 1 : 0; }

// ---------------- graph preprocessing ----------------
__global__ void k_init() {
    int i = blockIdx.x * blockDim.x + threadIdx.x;
    if (i < NODES) { g_degw[i] = 1.0f; g_cnt[i] = 0; g_fill[i] = 0; }
}

__global__ void k_edge_deg(const int* __restrict__ ei, const float* __restrict__ ew) {
    int e = blockIdx.x * blockDim.x + threadIdx.x;
    if (e < EDGES) {
        int dst = edge_val(ei, EDGES + e);
        atomicAdd(&g_degw[dst], ew[e]);
        atomicAdd(&g_cnt[dst], 1);
    }
}

__global__ void k_dis() {
    int i = blockIdx.x * blockDim.x + threadIdx.x;
    if (i < NODES) g_dis[i] = rsqrtf(g_degw[i]);   // deg >= 1 always (self-loop)
}

// exclusive scan of g_cnt -> g_rowptr. NODES = 1024 * 22 exactly; single block.
__global__ void k_scan() {
    __shared__ int ssum[1024];
    int t = threadIdx.x;
    int base = t * 22;
    int vals[22];
    int local = 0;
#pragma unroll
    for (int i = 0; i < 22; i++) { vals[i] = g_cnt[base + i]; local += vals[i]; }
    ssum[t] = local;
    __syncthreads();
    for (int off = 1; off < 1024; off <<= 1) {
        int v = (t >= off) ? ssum[t - off] : 0;
        __syncthreads();
        ssum[t] += v;
        __syncthreads();
    }
    int prefix = (t == 0) ? 0 : ssum[t - 1];
#pragma unroll
    for (int i = 0; i < 22; i++) { g_rowptr[base + i] = prefix; prefix += vals[i]; }
    if (t == 1023) g_rowptr[NODES] = prefix;
}

__global__ void k_fill(const int* __restrict__ ei, const float* __restrict__ ew) {
    int e = blockIdx.x * blockDim.x + threadIdx.x;
    if (e < EDGES) {
        int src = edge_val(ei, e);
        int dst = edge_val(ei, EDGES + e);
        int pos = g_rowptr[dst] + atomicAdd(&g_fill[dst], 1);
        g_csr_src[pos] = src;
        g_csr_w[pos]   = g_dis[src] * ew[e] * g_dis[dst];
    }
}

// ---------------- SpMM aggregation: out[n] = lrelu(bias + sum_e w*h[src]) ----------------
// one block (128 threads) per node; each thread owns one float4 of the 512-wide row.
__global__ __launch_bounds__(128) void k_agg(int hsel,
                                             const float* __restrict__ bias,
                                             int osel, int ostride) {
    const float* h = selbuf(hsel);
    float* out = selbuf(osel);
    int node = blockIdx.x;
    int f = threadIdx.x;                   // 0..127 float4 lanes
    float sw = g_dis[node]; sw *= sw;      // self-loop norm
    const float4* hrow = (const float4*)(h + (size_t)node * HID);
    float4 v = __ldg(hrow + f);
    float4 acc = make_float4(sw * v.x, sw * v.y, sw * v.z, sw * v.w);
    int s = g_rowptr[node], e = g_rowptr[node + 1];
    for (int j = s; j < e; j++) {
        int   src = g_csr_src[j];
        float w   = g_csr_w[j];
        float4 u = __ldg(((const float4*)(h + (size_t)src * HID)) + f);
        acc.x += w * u.x; acc.y += w * u.y; acc.z += w * u.z; acc.w += w * u.w;
    }
    float4 b = __ldg(((const float4*)bias) + f);
    acc.x = lrelu(acc.x + b.x);
    acc.y = lrelu(acc.y + b.y);
    acc.z = lrelu(acc.z + b.z);
    acc.w = lrelu(acc.w + b.w);
    *(float4*)(out + (size_t)node * ostride + 4 * f) = acc;
}

// copy x into cat[:, 512:572]
__global__ void k_catx(const float* __restrict__ x) {
    int node = blockIdx.x;
    int t = threadIdx.x;
    if (t < FEA) g_cat[(size_t)node * CATW + HID + t] = x[(size_t)node * FEA + t];
}

// ---------------- SGEMM: C = act(A[M,K] @ B[K,N] + bias) ----------------
// 64x64 tile, BK=16, 256 threads, 4x4 per thread. M % 64 == 0, N % 64 == 0 assumed.
template<bool BIAS, bool RELU>
__global__ __launch_bounds__(256) void sgemm64(const float* __restrict__ Aext, int asel,
                                               const float* __restrict__ B,
                                               const float* __restrict__ bias,
                                               int csel,
                                               int M, int N, int K) {
    const float* A = (asel == SEL_EXT) ? Aext : selbuf(asel);
    float* C = selbuf(csel);
    __shared__ float As[16][68];
    __shared__ float Bs[16][64];
    int tid = threadIdx.x;
    int bm = blockIdx.y * 64, bn = blockIdx.x * 64;
    int tx = tid & 15, ty = tid >> 4;
    int aRow = tid >> 2;
    int aK   = (tid & 3) * 4;

    float acc[4][4];
#pragma unroll
    for (int i = 0; i < 4; i++)
#pragma unroll
        for (int j = 0; j < 4; j++) acc[i][j] = 0.f;

    for (int k0 = 0; k0 < K; k0 += 16) {
        int kA = k0 + aK;
        const float* ap = A + (size_t)(bm + aRow) * K + kA;
        float4 av = make_float4(0.f, 0.f, 0.f, 0.f);
        if (kA + 3 < K) {
            av = *(const float4*)ap;
        } else {
            if (kA + 0 < K) av.x = ap[0];
            if (kA + 1 < K) av.y = ap[1];
            if (kA + 2 < K) av.z = ap[2];
            if (kA + 3 < K) av.w = ap[3];
        }
        As[aK + 0][aRow] = av.x;
        As[aK + 1][aRow] = av.y;
        As[aK + 2][aRow] = av.z;
        As[aK + 3][aRow] = av.w;
#pragma unroll
        for (int i = 0; i < 4; i++) {
            int idx = tid + i * 256;
            int bk = idx >> 6, bc = idx & 63;
            float v = 0.f;
            if (k0 + bk < K) v = B[(size_t)(k0 + bk) * N + bn + bc];
            Bs[bk][bc] = v;
        }
        __syncthreads();
#pragma unroll
        for (int kk = 0; kk < 16; kk++) {
            float a0 = As[kk][ty * 4 + 0], a1 = As[kk][ty * 4 + 1];
            float a2 = As[kk][ty * 4 + 2], a3 = As[kk][ty * 4 + 3];
            float b0 = Bs[kk][tx * 4 + 0], b1 = Bs[kk][tx * 4 + 1];
            float b2 = Bs[kk][tx * 4 + 2], b3 = Bs[kk][tx * 4 + 3];
            acc[0][0] += a0 * b0; acc[0][1] += a0 * b1; acc[0][2] += a0 * b2; acc[0][3] += a0 * b3;
            acc[1][0] += a1 * b0; acc[1][1] += a1 * b1; acc[1][2] += a1 * b2; acc[1][3] += a1 * b3;
            acc[2][0] += a2 * b0; acc[2][1] += a2 * b1; acc[2][2] += a2 * b2; acc[2][3] += a2 * b3;
            acc[3][0] += a3 * b0; acc[3][1] += a3 * b1; acc[3][2] += a3 * b2; acc[3][3] += a3 * b3;
        }
        __syncthreads();
    }

#pragma unroll
    for (int i = 0; i < 4; i++) {
        int row = bm + ty * 4 + i;
        int col = bn + tx * 4;
        float4 r = make_float4(acc[i][0], acc[i][1], acc[i][2], acc[i][3]);
        if (BIAS) {
            float4 bb = *(const float4*)(bias + col);
            r.x += bb.x; r.y += bb.y; r.z += bb.z; r.w += bb.w;
        }
        if (RELU) { r.x = lrelu(r.x); r.y = lrelu(r.y); r.z = lrelu(r.z); r.w = lrelu(r.w); }
        *(float4*)(C + (size_t)row * N + col) = r;
    }
}

// ---------------- head: logits = g_m0@Wo + bo, then log_softmax over 4 ----------------
__global__ __launch_bounds__(128) void k_final(const float* __restrict__ Wo,
                                               const float* __restrict__ bo,
                                               float* __restrict__ out) {
    int warp = threadIdx.x >> 5, lane = threadIdx.x & 31;
    int row = blockIdx.x * 4 + warp;
    const float* hr = g_m0 + (size_t)row * HID;
    float a0 = 0.f, a1 = 0.f, a2 = 0.f, a3 = 0.f;
    for (int k = lane; k < HID; k += 32) {
        float hv = hr[k];
        float4 w = ((const float4*)Wo)[k];
        a0 += hv * w.x; a1 += hv * w.y; a2 += hv * w.z; a3 += hv * w.w;
    }
#pragma unroll
    for (int off = 16; off; off >>= 1) {
        a0 += __shfl_xor_sync(0xffffffffu, a0, off);
        a1 += __shfl_xor_sync(0xffffffffu, a1, off);
        a2 += __shfl_xor_sync(0xffffffffu, a2, off);
        a3 += __shfl_xor_sync(0xffffffffu, a3, off);
    }
    if (lane == 0) {
        a0 += bo[0]; a1 += bo[1]; a2 += bo[2]; a3 += bo[3];
        float m = fmaxf(fmaxf(a0, a1), fmaxf(a2, a3));
        float s = expf(a0 - m) + expf(a1 - m) + expf(a2 - m) + expf(a3 - m);
        float lse = m + logf(s);
        out[row * 4 + 0] = a0 - lse;
        out[row * 4 + 1] = a1 - lse;
        out[row * 4 + 2] = a2 - lse;
        out[row * 4 + 3] = a3 - lse;
    }
}

// ---------------- launch ----------------
extern "C" void kernel_launch(void* const* d_in, const int* in_sizes, int n_in,
                              void* d_out, int out_size) {
    const float* x   = (const float*)d_in[0];
    const int*   ei  = (const int*)d_in[1];        // int32 OR int64 (probed on device)
    const float* ew  = (const float*)d_in[2];
    const float* W1  = (const float*)d_in[3];
    const float* b1  = (const float*)d_in[4];
    const float* W2  = (const float*)d_in[5];
    const float* b2  = (const float*)d_in[6];
    const float* Wf0 = (const float*)d_in[7];
    const float* bf0 = (const float*)d_in[8];
    const float* Wf1 = (const float*)d_in[9];
    const float* bf1 = (const float*)d_in[10];
    const float* Wf2 = (const float*)d_in[11];
    const float* bf2 = (const float*)d_in[12];
    const float* Wo  = (const float*)d_in[13];
    const float* bo  = (const float*)d_in[14];
    float* out = (float*)d_out;

    // dtype probe (samples words within the first 4096 int32s = safe for either dtype)
    k_probe<<<8, 256>>>(ei);
    k_probe_fin<<<1, 1>>>();

    // CSR build
    k_init<<<(NODES + 255) / 256, 256>>>();
    k_edge_deg<<<(EDGES + 255) / 256, 256>>>(ei, ew);
    k_dis<<<(NODES + 255) / 256, 256>>>();
    k_scan<<<1, 1024>>>();
    k_fill<<<(EDGES + 255) / 256, 256>>>(ei, ew);

    // conv1: bufA = x@W1 ; bufB = lrelu(agg(bufA) + b1)
    sgemm64<false, false><<<dim3(HID / 64, NODES / 64), 256>>>(x, SEL_EXT, W1, nullptr, SEL_A, NODES, HID, FEA);
    k_agg<<<NODES, 128>>>(SEL_A, b1, SEL_B, HID);

    // conv2: bufA = bufB@W2 ; cat[:, :512] = lrelu(agg(bufA) + b2)
    sgemm64<false, false><<<dim3(HID / 64, NODES / 64), 256>>>(nullptr, SEL_B, W2, nullptr, SEL_A, NODES, HID, HID);
    k_agg<<<NODES, 128>>>(SEL_A, b2, SEL_CAT, CATW);
    k_catx<<<NODES, 64>>>(x);

    // MLP (cat viewed as [1024, 12584])
    sgemm64<true, true><<<dim3(HID / 64, BATCH / 64), 256>>>(nullptr, SEL_CAT, Wf0, bf0, SEL_M0, BATCH, HID, FLATK);
    sgemm64<true, true><<<dim3(HID / 64, BATCH / 64), 256>>>(nullptr, SEL_M0, Wf1, bf1, SEL_M1, BATCH, HID, HID);
    sgemm64<true, true><<<dim3(HID / 64, BATCH / 64), 256>>>(nullptr, SEL_M1, Wf2, bf2, SEL_M0, BATCH, HID, HID);

    // head + log_softmax
    k_final<<<BATCH / 4, 128>>>(Wo, bo, out);
}